// round 3
// baseline (speedup 1.0000x reference)
#include <cuda_runtime.h>
#include <cstdint>

#define NN 50000
#define EE 600000
#define DIM 128
#define NCLS 40

// ---------------- scratch (static __device__, no allocation) ----------------
__device__ int   g_cnt[NN];
__device__ int   g_rowptr[NN + 1];
__device__ int   g_fill[NN];
__device__ int   g_srcs[EE];
__device__ float g_dinv[NN];
__device__ __align__(16) float g_h1[(size_t)NN * DIM];
__device__ __align__(16) float g_h2[(size_t)NN * DIM];

// ---------------- preprocessing ----------------
__global__ void k_zero() {
    int i = blockIdx.x * blockDim.x + threadIdx.x;
    if (i < NN) g_cnt[i] = 0;
}

__global__ void k_hist(const int* __restrict__ col) {
    int i = blockIdx.x * blockDim.x + threadIdx.x;
    if (i < EE) {
        unsigned c = (unsigned)col[i];
        if (c < NN) atomicAdd(&g_cnt[c], 1);
    }
}

__global__ void k_dinv() {
    int i = blockIdx.x * blockDim.x + threadIdx.x;
    if (i < NN) g_dinv[i] = rsqrtf((float)g_cnt[i] + 1.0f);
}

// single-block exclusive scan of g_cnt -> g_rowptr / g_fill (warp-shuffle based)
__global__ void k_scan() {
    __shared__ int wsum[32];
    __shared__ int carry_s;
    int t = threadIdx.x, lane = t & 31, w = t >> 5;
    if (t == 0) carry_s = 0;
    __syncthreads();
    for (int base = 0; base < NN; base += 1024) {
        int i = base + t;
        int v = (i < NN) ? g_cnt[i] : 0;
        int incl = v;
        #pragma unroll
        for (int off = 1; off < 32; off <<= 1) {
            int u = __shfl_up_sync(0xffffffffu, incl, off);
            if (lane >= off) incl += u;
        }
        if (lane == 31) wsum[w] = incl;
        __syncthreads();
        if (w == 0) {
            int s = wsum[lane];
            #pragma unroll
            for (int off = 1; off < 32; off <<= 1) {
                int u = __shfl_up_sync(0xffffffffu, s, off);
                if (lane >= off) s += u;
            }
            wsum[lane] = s;
        }
        __syncthreads();
        int woff = (w > 0) ? wsum[w - 1] : 0;
        int excl = carry_s + woff + incl - v;
        if (i < NN) { g_rowptr[i] = excl; g_fill[i] = excl; }
        __syncthreads();
        if (t == 0) carry_s += wsum[31];
        __syncthreads();
    }
    if (threadIdx.x == 0) g_rowptr[NN] = carry_s;
}

__global__ void k_scatter(const int* __restrict__ row,
                          const int* __restrict__ col) {
    int i = blockIdx.x * blockDim.x + threadIdx.x;
    if (i < EE) {
        unsigned c = (unsigned)col[i];
        unsigned r = (unsigned)row[i];
        if (c < NN && r < NN) {
            int p = atomicAdd(&g_fill[c], 1);
            g_srcs[p] = (int)r;
        }
    }
}

// ---------------- dense GEMM: C[n,128] = A[n,128] @ W[128,128]^T ----------------
// 96KB dynamic smem: Ws[k][o] (transposed W) + As[64][128]. 256 thr, 8x4 reg tile.
// A==nullptr -> read g_h2; C==nullptr -> write g_h1.
__global__ void __launch_bounds__(256) k_gemm(const float* __restrict__ A,
                                              const float* __restrict__ W,
                                              float* __restrict__ C, int n) {
    extern __shared__ float sm[];
    if (A == nullptr) A = g_h2;
    if (C == nullptr) C = g_h1;
    float* Ws = sm;               // [128][128], Ws[k*128+o] = W[o*128+k]
    float* As = sm + 128 * 128;   // [64][128]
    int t = threadIdx.x;
    int row0 = blockIdx.x * 64;

    #pragma unroll
    for (int p = 0; p < 16; p++) {
        int e = (t + p * 256) * 4;
        int o = e >> 7, k = e & 127;
        float4 wv = *(const float4*)(W + e);
        Ws[(k + 0) * 128 + o] = wv.x;
        Ws[(k + 1) * 128 + o] = wv.y;
        Ws[(k + 2) * 128 + o] = wv.z;
        Ws[(k + 3) * 128 + o] = wv.w;
    }
    #pragma unroll
    for (int p = 0; p < 8; p++) {
        int e = (t + p * 256) * 4;
        int r = e >> 7, k = e & 127;
        int gr = row0 + r;
        if (gr >= n) gr = n - 1;
        *(float4*)(As + e) = *(const float4*)(A + (size_t)gr * 128 + k);
    }
    __syncthreads();

    int tx = t & 31, ty = t >> 5;
    int o0 = tx * 4, r0 = ty * 8;
    float acc[8][4];
    #pragma unroll
    for (int i = 0; i < 8; i++)
        #pragma unroll
        for (int j = 0; j < 4; j++) acc[i][j] = 0.f;

    #pragma unroll 8
    for (int k = 0; k < 128; k++) {
        float4 wv = *(float4*)(Ws + k * 128 + o0);
        #pragma unroll
        for (int i = 0; i < 8; i++) {
            float a = As[(r0 + i) * 128 + k];   // warp-uniform -> smem broadcast
            acc[i][0] = fmaf(a, wv.x, acc[i][0]);
            acc[i][1] = fmaf(a, wv.y, acc[i][1]);
            acc[i][2] = fmaf(a, wv.z, acc[i][2]);
            acc[i][3] = fmaf(a, wv.w, acc[i][3]);
        }
    }
    #pragma unroll
    for (int i = 0; i < 8; i++) {
        int gr = row0 + r0 + i;
        if (gr < n) *(float4*)(C + (size_t)gr * 128 + o0) = *(float4*)&acc[i][0];
    }
}

// ---------------- CSR aggregation: warp-per-node gather, fused bias+relu ----------------
// reads g_h1, writes g_h2
__global__ void __launch_bounds__(256) k_agg(const float* __restrict__ bias) {
    int gw = (blockIdx.x * blockDim.x + threadIdx.x) >> 5;
    if (gw >= NN) return;
    int lane = threadIdx.x & 31;
    const float4* h4 = (const float4*)g_h1;
    float di = g_dinv[gw];
    float4 own = h4[gw * 32 + lane];
    float ax = di * own.x, ay = di * own.y, az = di * own.z, aw = di * own.w;
    int e = g_rowptr[gw], end = g_rowptr[gw + 1];
    for (; e < end; e++) {
        int s = g_srcs[e];
        float c = g_dinv[s];
        float4 v = h4[s * 32 + lane];
        ax = fmaf(c, v.x, ax);
        ay = fmaf(c, v.y, ay);
        az = fmaf(c, v.z, az);
        aw = fmaf(c, v.w, aw);
    }
    float4 b = ((const float4*)bias)[lane];
    float4 o;
    o.x = fmaxf(fmaf(di, ax, b.x), 0.f);
    o.y = fmaxf(fmaf(di, ay, b.y), 0.f);
    o.z = fmaxf(fmaf(di, az, b.z), 0.f);
    o.w = fmaxf(fmaf(di, aw, b.w), 0.f);
    ((float4*)g_h2)[gw * 32 + lane] = o;
}

// ---------------- final: logits + log_softmax, warp-per-node (reads g_h2) ----------------
__global__ void __launch_bounds__(256) k_final(const float* __restrict__ Wf,
                                               const float* __restrict__ bf,
                                               float* __restrict__ out) {
    __shared__ float WfT[128 * 40];   // WfT[k*40+c] = Wf[c*128+k]
    __shared__ float bfs[40];
    __shared__ __align__(16) float hs[8][128];
    int t = threadIdx.x;
    for (int e = t; e < NCLS * 128; e += 256) {
        int c = e >> 7, k = e & 127;
        WfT[k * 40 + c] = Wf[e];
    }
    if (t < NCLS) bfs[t] = bf[t];
    __syncthreads();

    int w = t >> 5, lane = t & 31;
    for (int node = blockIdx.x * 8 + w; node < NN; node += gridDim.x * 8) {
        ((float4*)hs[w])[lane] = ((const float4*)(g_h2 + (size_t)node * 128))[lane];
        __syncwarp();
        float acc0 = bfs[lane];
        float acc1 = (lane < 8) ? bfs[32 + lane] : 0.f;
        #pragma unroll 4
        for (int k = 0; k < 128; k++) {
            float hk = hs[w][k];                       // broadcast
            acc0 = fmaf(hk, WfT[k * 40 + lane], acc0);
            if (lane < 8) acc1 = fmaf(hk, WfT[k * 40 + 32 + lane], acc1);
        }
        float m = acc0;
        if (lane < 8) m = fmaxf(m, acc1);
        #pragma unroll
        for (int off = 16; off; off >>= 1)
            m = fmaxf(m, __shfl_xor_sync(0xffffffffu, m, off));
        float s = expf(acc0 - m) + ((lane < 8) ? expf(acc1 - m) : 0.f);
        #pragma unroll
        for (int off = 16; off; off >>= 1)
            s += __shfl_xor_sync(0xffffffffu, s, off);
        float lse = m + logf(s);
        out[(size_t)node * 40 + lane] = acc0 - lse;
        if (lane < 8) out[(size_t)node * 40 + 32 + lane] = acc1 - lse;
        __syncwarp();
    }
}

// ---------------- launch ----------------
extern "C" void kernel_launch(void* const* d_in, const int* in_sizes, int n_in,
                              void* d_out, int out_size) {
    const float* x  = (const float*)d_in[0];
    const int*   ei = (const int*)d_in[1];     // [2][E] materialized as int32
    const float* W1 = (const float*)d_in[2];
    const float* b1 = (const float*)d_in[3];
    const float* W2 = (const float*)d_in[4];
    const float* b2 = (const float*)d_in[5];
    const float* Wf = (const float*)d_in[6];
    const float* bf = (const float*)d_in[7];
    float* out = (float*)d_out;

    const int* row = ei;        // sources
    const int* col = ei + EE;   // targets

    k_zero<<<(NN + 255) / 256, 256>>>();
    k_hist<<<(EE + 255) / 256, 256>>>(col);
    k_dinv<<<(NN + 255) / 256, 256>>>();
    k_scan<<<1, 1024>>>();
    k_scatter<<<(EE + 255) / 256, 256>>>(row, col);

    cudaFuncSetAttribute(k_gemm, cudaFuncAttributeMaxDynamicSharedMemorySize, 98304);
    int gblocks = (NN + 63) / 64;
    int ablocks = (NN * 32 + 255) / 256;

    // layer 1: x @ W1^T -> g_h1 ; aggregate g_h1 -> g_h2 (+b1, relu)
    k_gemm<<<gblocks, 256, 98304>>>(x, W1, (float*)nullptr, NN);
    k_agg<<<ablocks, 256>>>(b1);
    // layer 2: g_h2 @ W2^T -> g_h1 ; aggregate -> g_h2 (+b2, relu)
    k_gemm<<<gblocks, 256, 98304>>>((const float*)nullptr, W2, (float*)nullptr, NN);
    k_agg<<<ablocks, 256>>>(b2);
    // final
    k_final<<<1184, 256>>>(Wf, bf, out);
}

// round 5
// speedup vs baseline: 1.0794x; 1.0794x over previous
#include <cuda_runtime.h>
#include <cstdint>

#define NN 50000
#define EE 600000
#define DIM 128
#define NCLS 40
#define SCAN_BLK 256
#define SCAN_NB ((NN + SCAN_BLK - 1) / SCAN_BLK)   // 196

// ---------------- scratch (static __device__, no allocation) ----------------
__device__ int   g_cnt[NN];
__device__ int   g_rowptr[NN + 1];
__device__ int   g_fill[NN];
__device__ int   g_srcs[EE];
__device__ int   g_bsum[SCAN_NB];
__device__ int   g_boff[SCAN_NB];
__device__ float g_dinv[NN];
__device__ __align__(16) float g_h1[(size_t)NN * DIM];
__device__ __align__(16) float g_h2[(size_t)NN * DIM];

// ---------------- preprocessing ----------------
__global__ void k_zero() {
    int i = blockIdx.x * blockDim.x + threadIdx.x;
    if (i < NN) g_cnt[i] = 0;
}

__global__ void k_hist(const int* __restrict__ col) {
    int i = blockIdx.x * blockDim.x + threadIdx.x;
    if (i < EE) {
        unsigned c = (unsigned)col[i];
        if (c < NN) atomicAdd(&g_cnt[c], 1);
    }
}

// stage 1: per-block exclusive scan of g_cnt -> g_rowptr (partial), block sums,
// fused dinv computation.
__global__ void __launch_bounds__(SCAN_BLK) k_scan1() {
    __shared__ int ws[8];
    int t = threadIdx.x, lane = t & 31, w = t >> 5;
    int i = blockIdx.x * SCAN_BLK + t;
    int v = (i < NN) ? g_cnt[i] : 0;
    if (i < NN) g_dinv[i] = rsqrtf((float)v + 1.0f);
    int incl = v;
    #pragma unroll
    for (int off = 1; off < 32; off <<= 1) {
        int u = __shfl_up_sync(0xffffffffu, incl, off);
        if (lane >= off) incl += u;
    }
    if (lane == 31) ws[w] = incl;
    __syncthreads();
    if (w == 0 && lane < 8) {
        int s = ws[lane];
        #pragma unroll
        for (int off = 1; off < 8; off <<= 1) {
            int u = __shfl_up_sync(0xffu, s, off);
            if (lane >= off) s += u;
        }
        ws[lane] = s;
    }
    __syncthreads();
    int excl = incl - v + (w ? ws[w - 1] : 0);
    if (i < NN) g_rowptr[i] = excl;
    if (t == 0) g_bsum[blockIdx.x] = ws[7];
}

// stage 2: exclusive scan of SCAN_NB block sums (single block), also total
__global__ void __launch_bounds__(SCAN_BLK) k_scan2() {
    __shared__ int ws[8];
    int t = threadIdx.x, lane = t & 31, w = t >> 5;
    int v = (t < SCAN_NB) ? g_bsum[t] : 0;
    int incl = v;
    #pragma unroll
    for (int off = 1; off < 32; off <<= 1) {
        int u = __shfl_up_sync(0xffffffffu, incl, off);
        if (lane >= off) incl += u;
    }
    if (lane == 31) ws[w] = incl;
    __syncthreads();
    if (w == 0 && lane < 8) {
        int s = ws[lane];
        #pragma unroll
        for (int off = 1; off < 8; off <<= 1) {
            int u = __shfl_up_sync(0xffu, s, off);
            if (lane >= off) s += u;
        }
        ws[lane] = s;
    }
    __syncthreads();
    int excl = incl - v + (w ? ws[w - 1] : 0);
    if (t < SCAN_NB) g_boff[t] = excl;
    if (t == SCAN_NB - 1) g_rowptr[NN] = excl + v;
}

// stage 3: add block offsets, produce final rowptr + fill
__global__ void __launch_bounds__(SCAN_BLK) k_scan3() {
    int i = blockIdx.x * SCAN_BLK + threadIdx.x;
    if (i < NN) {
        int e = g_rowptr[i] + g_boff[blockIdx.x];
        g_rowptr[i] = e;
        g_fill[i] = e;
    }
}

__global__ void k_scatter(const int* __restrict__ row,
                          const int* __restrict__ col) {
    int i = blockIdx.x * blockDim.x + threadIdx.x;
    if (i < EE) {
        unsigned c = (unsigned)col[i];
        unsigned r = (unsigned)row[i];
        if (c < NN && r < NN) {
            int p = atomicAdd(&g_fill[c], 1);
            g_srcs[p] = (int)r;
        }
    }
}

// ---------------- dense GEMM: C[n,128] = A[n,128] @ W[128,128]^T ----------------
// 96KB dynamic smem: Ws[k][o] (transposed W) + As[64][128]. 256 thr, 8x4 reg tile.
// A==nullptr -> read g_h2; C==nullptr -> write g_h1.
__global__ void __launch_bounds__(256) k_gemm(const float* __restrict__ A,
                                              const float* __restrict__ W,
                                              float* __restrict__ C, int n) {
    extern __shared__ float sm[];
    if (A == nullptr) A = g_h2;
    if (C == nullptr) C = g_h1;
    float* Ws = sm;               // [128][128], Ws[k*128+o] = W[o*128+k]
    float* As = sm + 128 * 128;   // [64][128]
    int t = threadIdx.x;
    int row0 = blockIdx.x * 64;

    #pragma unroll
    for (int p = 0; p < 16; p++) {
        int e = (t + p * 256) * 4;
        int o = e >> 7, k = e & 127;
        float4 wv = *(const float4*)(W + e);
        Ws[(k + 0) * 128 + o] = wv.x;
        Ws[(k + 1) * 128 + o] = wv.y;
        Ws[(k + 2) * 128 + o] = wv.z;
        Ws[(k + 3) * 128 + o] = wv.w;
    }
    #pragma unroll
    for (int p = 0; p < 8; p++) {
        int e = (t + p * 256) * 4;
        int r = e >> 7, k = e & 127;
        int gr = row0 + r;
        if (gr >= n) gr = n - 1;
        *(float4*)(As + e) = *(const float4*)(A + (size_t)gr * 128 + k);
    }
    __syncthreads();

    int tx = t & 31, ty = t >> 5;
    int o0 = tx * 4, r0 = ty * 8;
    float acc[8][4];
    #pragma unroll
    for (int i = 0; i < 8; i++)
        #pragma unroll
        for (int j = 0; j < 4; j++) acc[i][j] = 0.f;

    #pragma unroll 2
    for (int k4 = 0; k4 < 128; k4 += 4) {
        float4 w0 = *(float4*)(Ws + (k4 + 0) * 128 + o0);
        float4 w1 = *(float4*)(Ws + (k4 + 1) * 128 + o0);
        float4 w2 = *(float4*)(Ws + (k4 + 2) * 128 + o0);
        float4 w3 = *(float4*)(Ws + (k4 + 3) * 128 + o0);
        #pragma unroll
        for (int i = 0; i < 8; i++) {
            float4 a = *(float4*)(As + (r0 + i) * 128 + k4);   // warp-uniform broadcast
            acc[i][0] = fmaf(a.x, w0.x, acc[i][0]);
            acc[i][1] = fmaf(a.x, w0.y, acc[i][1]);
            acc[i][2] = fmaf(a.x, w0.z, acc[i][2]);
            acc[i][3] = fmaf(a.x, w0.w, acc[i][3]);
            acc[i][0] = fmaf(a.y, w1.x, acc[i][0]);
            acc[i][1] = fmaf(a.y, w1.y, acc[i][1]);
            acc[i][2] = fmaf(a.y, w1.z, acc[i][2]);
            acc[i][3] = fmaf(a.y, w1.w, acc[i][3]);
            acc[i][0] = fmaf(a.z, w2.x, acc[i][0]);
            acc[i][1] = fmaf(a.z, w2.y, acc[i][1]);
            acc[i][2] = fmaf(a.z, w2.z, acc[i][2]);
            acc[i][3] = fmaf(a.z, w2.w, acc[i][3]);
            acc[i][0] = fmaf(a.w, w3.x, acc[i][0]);
            acc[i][1] = fmaf(a.w, w3.y, acc[i][1]);
            acc[i][2] = fmaf(a.w, w3.z, acc[i][2]);
            acc[i][3] = fmaf(a.w, w3.w, acc[i][3]);
        }
    }
    #pragma unroll
    for (int i = 0; i < 8; i++) {
        int gr = row0 + r0 + i;
        if (gr < n) *(float4*)(C + (size_t)gr * 128 + o0) = *(float4*)&acc[i][0];
    }
}

// ---------------- CSR aggregation: warp-per-node gather, fused bias+relu ----------------
// reads g_h1, writes g_h2. Edge loop unrolled x2 for MLP.
__global__ void __launch_bounds__(256) k_agg(const float* __restrict__ bias) {
    int gw = (blockIdx.x * blockDim.x + threadIdx.x) >> 5;
    if (gw >= NN) return;
    int lane = threadIdx.x & 31;
    const float4* h4 = (const float4*)g_h1;
    float di = g_dinv[gw];
    float4 own = h4[gw * 32 + lane];
    float ax = di * own.x, ay = di * own.y, az = di * own.z, aw = di * own.w;
    int e = g_rowptr[gw], end = g_rowptr[gw + 1];
    for (; e + 1 < end; e += 2) {
        int s0 = g_srcs[e];
        int s1 = g_srcs[e + 1];
        float c0 = g_dinv[s0];
        float c1 = g_dinv[s1];
        float4 v0 = h4[s0 * 32 + lane];
        float4 v1 = h4[s1 * 32 + lane];
        ax = fmaf(c0, v0.x, ax);  ay = fmaf(c0, v0.y, ay);
        az = fmaf(c0, v0.z, az);  aw = fmaf(c0, v0.w, aw);
        ax = fmaf(c1, v1.x, ax);  ay = fmaf(c1, v1.y, ay);
        az = fmaf(c1, v1.z, az);  aw = fmaf(c1, v1.w, aw);
    }
    if (e < end) {
        int s = g_srcs[e];
        float c = g_dinv[s];
        float4 v = h4[s * 32 + lane];
        ax = fmaf(c, v.x, ax);  ay = fmaf(c, v.y, ay);
        az = fmaf(c, v.z, az);  aw = fmaf(c, v.w, aw);
    }
    float4 b = ((const float4*)bias)[lane];
    float4 o;
    o.x = fmaxf(fmaf(di, ax, b.x), 0.f);
    o.y = fmaxf(fmaf(di, ay, b.y), 0.f);
    o.z = fmaxf(fmaf(di, az, b.z), 0.f);
    o.w = fmaxf(fmaf(di, aw, b.w), 0.f);
    ((float4*)g_h2)[gw * 32 + lane] = o;
}

// ---------------- final: logits + log_softmax, warp-per-node (reads g_h2) ----------------
__global__ void __launch_bounds__(256) k_final(const float* __restrict__ Wf,
                                               const float* __restrict__ bf,
                                               float* __restrict__ out) {
    __shared__ float WfT[128 * 40];   // WfT[k*40+c] = Wf[c*128+k]
    __shared__ float bfs[40];
    __shared__ __align__(16) float hs[8][128];
    int t = threadIdx.x;
    for (int e = t; e < NCLS * 128; e += 256) {
        int c = e >> 7, k = e & 127;
        WfT[k * 40 + c] = Wf[e];
    }
    if (t < NCLS) bfs[t] = bf[t];
    __syncthreads();

    int w = t >> 5, lane = t & 31;
    for (int node = blockIdx.x * 8 + w; node < NN; node += gridDim.x * 8) {
        ((float4*)hs[w])[lane] = ((const float4*)(g_h2 + (size_t)node * 128))[lane];
        __syncwarp();
        float acc0 = bfs[lane];
        float acc1 = (lane < 8) ? bfs[32 + lane] : 0.f;
        #pragma unroll 4
        for (int k = 0; k < 128; k++) {
            float hk = hs[w][k];                       // broadcast
            acc0 = fmaf(hk, WfT[k * 40 + lane], acc0);
            if (lane < 8) acc1 = fmaf(hk, WfT[k * 40 + 32 + lane], acc1);
        }
        float m = acc0;
        if (lane < 8) m = fmaxf(m, acc1);
        #pragma unroll
        for (int off = 16; off; off >>= 1)
            m = fmaxf(m, __shfl_xor_sync(0xffffffffu, m, off));
        float s = __expf(acc0 - m) + ((lane < 8) ? __expf(acc1 - m) : 0.f);
        #pragma unroll
        for (int off = 16; off; off >>= 1)
            s += __shfl_xor_sync(0xffffffffu, s, off);
        float lse = m + __logf(s);
        out[(size_t)node * 40 + lane] = acc0 - lse;
        if (lane < 8) out[(size_t)node * 40 + 32 + lane] = acc1 - lse;
        __syncwarp();
    }
}

// ---------------- launch ----------------
extern "C" void kernel_launch(void* const* d_in, const int* in_sizes, int n_in,
                              void* d_out, int out_size) {
    const float* x  = (const float*)d_in[0];
    const int*   ei = (const int*)d_in[1];     // [2][E] int32
    const float* W1 = (const float*)d_in[2];
    const float* b1 = (const float*)d_in[3];
    const float* W2 = (const float*)d_in[4];
    const float* b2 = (const float*)d_in[5];
    const float* Wf = (const float*)d_in[6];
    const float* bf = (const float*)d_in[7];
    float* out = (float*)d_out;

    const int* row = ei;        // sources
    const int* col = ei + EE;   // targets

    cudaFuncSetAttribute(k_gemm, cudaFuncAttributeMaxDynamicSharedMemorySize, 98304);
    int gblocks = (NN + 63) / 64;
    int ablocks = (NN * 32 + 255) / 256;

    // preprocessing (5 launches), then GEMM1 as launch #6 -> ncu -s 5 -c 1 captures it
    k_zero<<<(NN + 255) / 256, 256>>>();                 // 1
    k_hist<<<(EE + 255) / 256, 256>>>(col);              // 2
    k_scan1<<<SCAN_NB, SCAN_BLK>>>();                    // 3 (fuses dinv)
    k_scan2<<<1, SCAN_BLK>>>();                          // 4
    k_scan3<<<SCAN_NB, SCAN_BLK>>>();                    // 5
    k_gemm<<<gblocks, 256, 98304>>>(x, W1, (float*)nullptr, NN);   // 6  x@W1^T -> g_h1
    k_scatter<<<(EE + 255) / 256, 256>>>(row, col);      // 7 (independent of gemm)
    k_agg<<<ablocks, 256>>>(b1);                         // 8  g_h1 -> g_h2 (+b1, relu)
    k_gemm<<<gblocks, 256, 98304>>>((const float*)nullptr, W2, (float*)nullptr, NN); // 9
    k_agg<<<ablocks, 256>>>(b2);                         // 10
    k_final<<<1184, 256>>>(Wf, bf, out);                 // 11
}

// round 8
// speedup vs baseline: 1.7526x; 1.6238x over previous
#include <cuda_runtime.h>
#include <cuda_bf16.h>
#include <cstdint>

#define NN 50000
#define EE 600000
#define DIM 128
#define NCLS 40
#define SCAN_BLK 256
#define SCAN_NB ((NN + SCAN_BLK - 1) / SCAN_BLK)   // 196

// ---------------- scratch (static __device__, no allocation) ----------------
__device__ int   g_cnt[NN];
__device__ int   g_rowptr[NN + 1];
__device__ int   g_fill[NN];
__device__ int   g_srcs[EE];
__device__ int   g_bsum[SCAN_NB];
__device__ int   g_boff[SCAN_NB];
__device__ float g_dinv[NN];
__device__ __align__(16) float g_h1[(size_t)NN * DIM];
__device__ __align__(16) float g_h2[(size_t)NN * DIM];

// ---------------- preprocessing ----------------
__global__ void k_zero() {
    int i = blockIdx.x * blockDim.x + threadIdx.x;
    if (i < NN) g_cnt[i] = 0;
}

__global__ void k_hist(const int* __restrict__ col) {
    int i = blockIdx.x * blockDim.x + threadIdx.x;
    if (i < EE) {
        unsigned c = (unsigned)col[i];
        if (c < NN) atomicAdd(&g_cnt[c], 1);
    }
}

__global__ void __launch_bounds__(SCAN_BLK) k_scan1() {
    __shared__ int ws[8];
    int t = threadIdx.x, lane = t & 31, w = t >> 5;
    int i = blockIdx.x * SCAN_BLK + t;
    int v = (i < NN) ? g_cnt[i] : 0;
    if (i < NN) g_dinv[i] = rsqrtf((float)v + 1.0f);
    int incl = v;
    #pragma unroll
    for (int off = 1; off < 32; off <<= 1) {
        int u = __shfl_up_sync(0xffffffffu, incl, off);
        if (lane >= off) incl += u;
    }
    if (lane == 31) ws[w] = incl;
    __syncthreads();
    if (w == 0 && lane < 8) {
        int s = ws[lane];
        #pragma unroll
        for (int off = 1; off < 8; off <<= 1) {
            int u = __shfl_up_sync(0xffu, s, off);
            if (lane >= off) s += u;
        }
        ws[lane] = s;
    }
    __syncthreads();
    int excl = incl - v + (w ? ws[w - 1] : 0);
    if (i < NN) g_rowptr[i] = excl;
    if (t == 0) g_bsum[blockIdx.x] = ws[7];
}

__global__ void __launch_bounds__(SCAN_BLK) k_scan2() {
    __shared__ int ws[8];
    int t = threadIdx.x, lane = t & 31, w = t >> 5;
    int v = (t < SCAN_NB) ? g_bsum[t] : 0;
    int incl = v;
    #pragma unroll
    for (int off = 1; off < 32; off <<= 1) {
        int u = __shfl_up_sync(0xffffffffu, incl, off);
        if (lane >= off) incl += u;
    }
    if (lane == 31) ws[w] = incl;
    __syncthreads();
    if (w == 0 && lane < 8) {
        int s = ws[lane];
        #pragma unroll
        for (int off = 1; off < 8; off <<= 1) {
            int u = __shfl_up_sync(0xffu, s, off);
            if (lane >= off) s += u;
        }
        ws[lane] = s;
    }
    __syncthreads();
    int excl = incl - v + (w ? ws[w - 1] : 0);
    if (t < SCAN_NB) g_boff[t] = excl;
    if (t == SCAN_NB - 1) g_rowptr[NN] = excl + v;
}

__global__ void __launch_bounds__(SCAN_BLK) k_scan3() {
    int i = blockIdx.x * SCAN_BLK + threadIdx.x;
    if (i < NN) {
        int e = g_rowptr[i] + g_boff[blockIdx.x];
        g_rowptr[i] = e;
        g_fill[i] = e;
    }
}

__global__ void k_scatter(const int* __restrict__ row,
                          const int* __restrict__ col) {
    int i = blockIdx.x * blockDim.x + threadIdx.x;
    if (i < EE) {
        unsigned c = (unsigned)col[i];
        unsigned r = (unsigned)row[i];
        if (c < NN && r < NN) {
            int p = atomicAdd(&g_fill[c], 1);
            g_srcs[p] = (int)r;
        }
    }
}

// ---------------- mma.sync GEMM: C[n,128] = A[n,128] @ W[128,128]^T ----------------
// split-bf16 3-term: D = Ah@Bh + Ah@Bl + Al@Bh, fp32 accumulate.
// SMEM: 4 buffers [128 rows][136 halves] (8-half pad -> conflict-free frag LDS).
#define PAD_W 68                         // u32 words per row
#define BUF_BYTES (128 * PAD_W * 4)      // 34816
#define SM_AH 0
#define SM_AL (SM_AH + BUF_BYTES)
#define SM_BH (SM_AL + BUF_BYTES)
#define SM_BL (SM_BH + BUF_BYTES)
#define SM_TOTAL (SM_BL + BUF_BYTES)     // 139264

__device__ __forceinline__ void split2(float a, unsigned& hi, unsigned& lo, int sh) {
    __nv_bfloat16 hb = __float2bfloat16(a);
    float hf = __bfloat162float(hb);
    __nv_bfloat16 lb = __float2bfloat16(a - hf);
    hi |= (unsigned)__bfloat16_as_ushort(hb) << sh;
    lo |= (unsigned)__bfloat16_as_ushort(lb) << sh;
}

__device__ __forceinline__ void mma_bf16(float* d, const unsigned* a, unsigned b0, unsigned b1) {
    asm volatile(
        "mma.sync.aligned.m16n8k16.row.col.f32.bf16.bf16.f32 "
        "{%0,%1,%2,%3}, {%4,%5,%6,%7}, {%8,%9}, {%0,%1,%2,%3};"
        : "+f"(d[0]), "+f"(d[1]), "+f"(d[2]), "+f"(d[3])
        : "r"(a[0]), "r"(a[1]), "r"(a[2]), "r"(a[3]), "r"(b0), "r"(b1));
}

__global__ void __launch_bounds__(256)
k_mmagemm(const float* __restrict__ A, const float* __restrict__ W,
          float* __restrict__ C, int n) {
    extern __shared__ __align__(16) char sm[];
    if (A == nullptr) A = g_h2;
    if (C == nullptr) C = g_h1;
    uint32_t* AHw = (uint32_t*)(sm + SM_AH);
    uint32_t* ALw = (uint32_t*)(sm + SM_AL);
    uint32_t* BHw = (uint32_t*)(sm + SM_BH);
    uint32_t* BLw = (uint32_t*)(sm + SM_BL);
    int t = threadIdx.x, wid = t >> 5, lane = t & 31;
    int row0 = blockIdx.x * 128;

    // ---- load + split A tile (128 rows x 128 k) and W (128 out x 128 k) ----
    const float4* A4 = (const float4*)A;
    const float4* W4 = (const float4*)W;
    #pragma unroll
    for (int p = 0; p < 16; p++) {
        int e = t + p * 256;
        int r = e >> 5, k4 = e & 31;     // row, k/4
        int gr = row0 + r;
        if (gr >= n) gr = n - 1;
        float4 a = A4[(size_t)gr * 32 + k4];
        unsigned h0 = 0, l0 = 0, h1 = 0, l1 = 0;
        split2(a.x, h0, l0, 0);  split2(a.y, h0, l0, 16);
        split2(a.z, h1, l1, 0);  split2(a.w, h1, l1, 16);
        int wo = r * PAD_W + k4 * 2;
        *(uint2*)(AHw + wo) = make_uint2(h0, h1);
        *(uint2*)(ALw + wo) = make_uint2(l0, l1);

        float4 b = W4[(size_t)r * 32 + k4];
        h0 = l0 = h1 = l1 = 0;
        split2(b.x, h0, l0, 0);  split2(b.y, h0, l0, 16);
        split2(b.z, h1, l1, 0);  split2(b.w, h1, l1, 16);
        *(uint2*)(BHw + wo) = make_uint2(h0, h1);
        *(uint2*)(BLw + wo) = make_uint2(l0, l1);
    }
    __syncthreads();

    // ---- compute: warp wid owns rows [wid*16, wid*16+16) x all 128 cols ----
    int grp = lane >> 2, tig = lane & 3;
    int arow = wid * 16 + grp;           // A fragment base row
    float acc[16][4];
    #pragma unroll
    for (int i = 0; i < 16; i++)
        #pragma unroll
        for (int j = 0; j < 4; j++) acc[i][j] = 0.f;

    #pragma unroll
    for (int ks = 0; ks < 8; ks++) {
        int kw = ks * 8 + tig;           // word index of k=ks*16+2*tig
        unsigned ah[4], al[4];
        int a0 = arow * PAD_W + kw;
        ah[0] = AHw[a0];              al[0] = ALw[a0];
        ah[1] = AHw[a0 + 8 * PAD_W];  al[1] = ALw[a0 + 8 * PAD_W];
        ah[2] = AHw[a0 + 4];          al[2] = ALw[a0 + 4];
        ah[3] = AHw[a0 + 8 * PAD_W + 4]; al[3] = ALw[a0 + 8 * PAD_W + 4];
        #pragma unroll
        for (int nt = 0; nt < 16; nt++) {
            int b0i = (nt * 8 + grp) * PAD_W + kw;
            unsigned bh0 = BHw[b0i], bh1 = BHw[b0i + 4];
            unsigned bl0 = BLw[b0i], bl1 = BLw[b0i + 4];
            mma_bf16(acc[nt], ah, bh0, bh1);
            mma_bf16(acc[nt], ah, bl0, bl1);
            mma_bf16(acc[nt], al, bh0, bh1);
        }
    }

    // ---- epilogue: direct stores (c0,c1 at row grp; c2,c3 at row grp+8) ----
    int gr0 = row0 + wid * 16 + grp;
    int gr1 = gr0 + 8;
    #pragma unroll
    for (int nt = 0; nt < 16; nt++) {
        int cc = nt * 8 + 2 * tig;
        if (gr0 < n) *(float2*)(C + (size_t)gr0 * 128 + cc) = make_float2(acc[nt][0], acc[nt][1]);
        if (gr1 < n) *(float2*)(C + (size_t)gr1 * 128 + cc) = make_float2(acc[nt][2], acc[nt][3]);
    }
}

// ---------------- CSR aggregation: warp-per-node gather, fused bias+relu ----------------
__global__ void __launch_bounds__(256) k_agg(const float* __restrict__ bias) {
    int gw = (blockIdx.x * blockDim.x + threadIdx.x) >> 5;
    if (gw >= NN) return;
    int lane = threadIdx.x & 31;
    const float4* h4 = (const float4*)g_h1;
    float di = g_dinv[gw];
    float4 own = h4[gw * 32 + lane];
    float ax = di * own.x, ay = di * own.y, az = di * own.z, aw = di * own.w;
    int e = g_rowptr[gw], end = g_rowptr[gw + 1];
    for (; e + 1 < end; e += 2) {
        int s0 = g_srcs[e];
        int s1 = g_srcs[e + 1];
        float c0 = g_dinv[s0];
        float c1 = g_dinv[s1];
        float4 v0 = h4[s0 * 32 + lane];
        float4 v1 = h4[s1 * 32 + lane];
        ax = fmaf(c0, v0.x, ax);  ay = fmaf(c0, v0.y, ay);
        az = fmaf(c0, v0.z, az);  aw = fmaf(c0, v0.w, aw);
        ax = fmaf(c1, v1.x, ax);  ay = fmaf(c1, v1.y, ay);
        az = fmaf(c1, v1.z, az);  aw = fmaf(c1, v1.w, aw);
    }
    if (e < end) {
        int s = g_srcs[e];
        float c = g_dinv[s];
        float4 v = h4[s * 32 + lane];
        ax = fmaf(c, v.x, ax);  ay = fmaf(c, v.y, ay);
        az = fmaf(c, v.z, az);  aw = fmaf(c, v.w, aw);
    }
    float4 b = ((const float4*)bias)[lane];
    float4 o;
    o.x = fmaxf(fmaf(di, ax, b.x), 0.f);
    o.y = fmaxf(fmaf(di, ay, b.y), 0.f);
    o.z = fmaxf(fmaf(di, az, b.z), 0.f);
    o.w = fmaxf(fmaf(di, aw, b.w), 0.f);
    ((float4*)g_h2)[gw * 32 + lane] = o;
}

// ---------------- final: logits + log_softmax, warp-per-node (reads g_h2) ----------------
__global__ void __launch_bounds__(256) k_final(const float* __restrict__ Wf,
                                               const float* __restrict__ bf,
                                               float* __restrict__ out) {
    __shared__ float WfT[128 * 40];
    __shared__ float bfs[40];
    __shared__ __align__(16) float hs[8][128];
    int t = threadIdx.x;
    for (int e = t; e < NCLS * 128; e += 256) {
        int c = e >> 7, k = e & 127;
        WfT[k * 40 + c] = Wf[e];
    }
    if (t < NCLS) bfs[t] = bf[t];
    __syncthreads();

    int w = t >> 5, lane = t & 31;
    for (int node = blockIdx.x * 8 + w; node < NN; node += gridDim.x * 8) {
        ((float4*)hs[w])[lane] = ((const float4*)(g_h2 + (size_t)node * 128))[lane];
        __syncwarp();
        float acc0 = bfs[lane];
        float acc1 = (lane < 8) ? bfs[32 + lane] : 0.f;
        #pragma unroll 4
        for (int k = 0; k < 128; k++) {
            float hk = hs[w][k];
            acc0 = fmaf(hk, WfT[k * 40 + lane], acc0);
            if (lane < 8) acc1 = fmaf(hk, WfT[k * 40 + 32 + lane], acc1);
        }
        float m = acc0;
        if (lane < 8) m = fmaxf(m, acc1);
        #pragma unroll
        for (int off = 16; off; off >>= 1)
            m = fmaxf(m, __shfl_xor_sync(0xffffffffu, m, off));
        float s = __expf(acc0 - m) + ((lane < 8) ? __expf(acc1 - m) : 0.f);
        #pragma unroll
        for (int off = 16; off; off >>= 1)
            s += __shfl_xor_sync(0xffffffffu, s, off);
        float lse = m + __logf(s);
        out[(size_t)node * 40 + lane] = acc0 - lse;
        if (lane < 8) out[(size_t)node * 40 + 32 + lane] = acc1 - lse;
        __syncwarp();
    }
}

// ---------------- launch ----------------
extern "C" void kernel_launch(void* const* d_in, const int* in_sizes, int n_in,
                              void* d_out, int out_size) {
    const float* x  = (const float*)d_in[0];
    const int*   ei = (const int*)d_in[1];
    const float* W1 = (const float*)d_in[2];
    const float* b1 = (const float*)d_in[3];
    const float* W2 = (const float*)d_in[4];
    const float* b2 = (const float*)d_in[5];
    const float* Wf = (const float*)d_in[6];
    const float* bf = (const float*)d_in[7];
    float* out = (float*)d_out;

    const int* row = ei;        // sources
    const int* col = ei + EE;   // targets

    cudaFuncSetAttribute(k_mmagemm, cudaFuncAttributeMaxDynamicSharedMemorySize, SM_TOTAL);
    int gblocks = (NN + 127) / 128;   // 391
    int ablocks = (NN * 32 + 255) / 256;

    // ncu empirically captures launch #4 -> put GEMM1 there
    k_zero<<<(NN + 255) / 256, 256>>>();                         // 1
    k_hist<<<(EE + 255) / 256, 256>>>(col);                      // 2
    k_scan1<<<SCAN_NB, SCAN_BLK>>>();                            // 3
    k_mmagemm<<<gblocks, 256, SM_TOTAL>>>(x, W1, (float*)nullptr, NN);  // 4 <- profiled
    k_scan2<<<1, SCAN_BLK>>>();                                  // 5
    k_scan3<<<SCAN_NB, SCAN_BLK>>>();                            // 6
    k_scatter<<<(EE + 255) / 256, 256>>>(row, col);              // 7
    k_agg<<<ablocks, 256>>>(b1);                                 // 8
    k_mmagemm<<<gblocks, 256, SM_TOTAL>>>((const float*)nullptr, W2, (float*)nullptr, NN); // 9
    k_agg<<<ablocks, 256>>>(b2);                                 // 10
    k_final<<<1184, 256>>>(Wf, bf, out);                         // 11
}